// round 1
// baseline (speedup 1.0000x reference)
#include <cuda_runtime.h>

// Problem constants (from reference)
#define B_ROWS   65536
#define C_COLS   300
#define A_DIM    32
#define XSTRIDE  600            // X row = [options(300) | cards(300)]

#define NWARPS   16
#define THREADS  (NWARPS * 32)
#define RPG      4              // rows per warp group
#define NGROUPS  (B_ROWS / RPG)
#define GRID     148

// SMEM layout strides (floats)
#define WT_STRIDE 308           // Wt[a][c], pad 300->308: float4 aligned + conflict-free LDS.128
#define WS_STRIDE 34            // Ws[c][a], pad 32->34: 8B aligned, low-conflict ldg by column index
#define CB_STRIDE 304           // cards row pad 300->304 (16B aligned rows)
#define IDXCAP    96            // max nonzero options tracked per row (P(exceed) ~ 1e-55)

#define OFF_WT    0
#define OFF_WS    (A_DIM * WT_STRIDE)                        // 9856
#define OFF_WARP  (OFF_WS + C_COLS * WS_STRIDE)              // 20056
// per-warp: cards[4][304] + ap[4][32] + outbuf[304] + idx[4][96]
#define WARP_FLOATS (RPG*CB_STRIDE + RPG*32 + 304 + RPG*IDXCAP)   // 2032
#define SMEM_FLOATS (OFF_WARP + NWARPS * WARP_FLOATS)        // 52568
#define SMEM_BYTES  (SMEM_FLOATS * 4)                        // 210272 B < 227 KB

__device__ __forceinline__ void fma2(unsigned long long& d,
                                     unsigned long long a,
                                     unsigned long long b) {
    asm("fma.rn.f32x2 %0, %1, %2, %0;" : "+l"(d) : "l"(a), "l"(b));
}

__device__ __forceinline__ float2 unpack2(unsigned long long v) {
    float2 r;
    asm("mov.b64 {%0, %1}, %2;" : "=f"(r.x), "=f"(r.y) : "l"(v));
    return r;
}

__global__ __launch_bounds__(THREADS, 1)
void draftbot_kernel(const float* __restrict__ X,
                     const float* __restrict__ W,
                     float* __restrict__ Out)
{
    extern __shared__ float smem[];
    float* Wt = smem + OFF_WT;   // [32][308]  (transposed, c-contiguous)
    float* Ws = smem + OFF_WS;   // [300][34]  (a-contiguous)

    const int tid  = threadIdx.x;
    const int lane = tid & 31;
    const int warp = tid >> 5;

    // Stage W into both layouts (once per CTA)
    for (int e = tid; e < C_COLS * A_DIM; e += THREADS) {
        float w = W[e];
        int c = e >> 5, a = e & 31;
        Wt[a * WT_STRIDE + c] = w;
        Ws[c * WS_STRIDE + a] = w;
    }
    __syncthreads();

    float* wbase   = smem + OFF_WARP + warp * WARP_FLOATS;
    float* cardbuf = wbase;                       // [4][304]
    float* apbuf   = wbase + RPG * CB_STRIDE;     // [4][32]
    float* outbuf  = apbuf + RPG * 32;            // [304]
    int*   idxbuf  = (int*)(outbuf + 304);        // [4][96]

    const unsigned FULL   = 0xffffffffu;
    const unsigned ltmask = (1u << lane) - 1u;
    const int gwarp     = blockIdx.x * NWARPS + warp;
    const int warpTotal = GRID * NWARPS;

    for (int g = gwarp; g < NGROUPS; g += warpTotal) {
        const int row0 = g * RPG;
        int cnt[RPG];

        // ---------- stage cards + compact nonzero option columns ----------
        #pragma unroll
        for (int r = 0; r < RPG; r++) {
            const float4* osrc = (const float4*)(X + (size_t)(row0 + r) * XSTRIDE);
            const float4* csrc = (const float4*)(X + (size_t)(row0 + r) * XSTRIDE + C_COLS);
            float* cb = cardbuf + r * CB_STRIDE;
            int cn = 0;
            #pragma unroll
            for (int t = 0; t < 3; t++) {
                int  gi = lane + 32 * t;
                bool v  = gi < 75;                 // 300/4 = 75 float4 per row
                float4 cv = v ? csrc[gi] : make_float4(0.f, 0.f, 0.f, 0.f);
                float4 ov = v ? osrc[gi] : make_float4(0.f, 0.f, 0.f, 0.f);
                if (v) *(float4*)(cb + 4 * gi) = cv;
                float ovals[4] = {ov.x, ov.y, ov.z, ov.w};
                #pragma unroll
                for (int i = 0; i < 4; i++) {
                    bool f = (ovals[i] != 0.0f);
                    unsigned m = __ballot_sync(FULL, f);
                    if (f) {
                        int pos = cn + __popc(m & ltmask);
                        if (pos < IDXCAP) idxbuf[r * IDXCAP + pos] = 4 * gi + i;
                    }
                    cn += __popc(m);
                }
            }
            cnt[r] = (cn < IDXCAP) ? cn : IDXCAP;
        }
        __syncwarp();

        // ---------- phase 1: ap = cards @ W + 1  (lane = a, f32x2 over column pairs) ----------
        unsigned long long acc[RPG];
        #pragma unroll
        for (int r = 0; r < RPG; r++) acc[r] = 0ull;

        const ulonglong2* wrow = (const ulonglong2*)(Wt + lane * WT_STRIDE);
        #pragma unroll 5
        for (int t = 0; t < 75; t++) {            // 4 columns per iter
            ulonglong2 wv = wrow[t];              // {w[c],w[c+1]},{w[c+2],w[c+3]} for a=lane
            #pragma unroll
            for (int r = 0; r < RPG; r++) {
                ulonglong2 cv = *(const ulonglong2*)(cardbuf + r * CB_STRIDE + 4 * t);
                fma2(acc[r], cv.x, wv.x);
                fma2(acc[r], cv.y, wv.y);
            }
        }
        #pragma unroll
        for (int r = 0; r < RPG; r++) {
            float2 a2 = unpack2(acc[r]);
            apbuf[r * 32 + lane] = a2.x + a2.y + 1.0f;
        }
        __syncwarp();

        // ---------- phase 2: sparse scores + masked log-softmax + writeback ----------
        #pragma unroll 1
        for (int r = 0; r < RPG; r++) {
            const int cn = cnt[r];
            float sc[3];
            int   cj[3];
            #pragma unroll
            for (int ch = 0; ch < 3; ch++) { sc[ch] = 0.0f; cj[ch] = -1; }

            float m = 0.0f;   // row max; 0 accounts for the always-present zero entries
            #pragma unroll 1
            for (int ch = 0; ch < 3 && ch * 32 < cn; ch++) {
                int  j   = ch * 32 + lane;
                bool val = j < cn;
                int  c   = val ? idxbuf[r * IDXCAP + j] : 0;
                unsigned long long s2 = 0ull;
                const unsigned long long* wp  = (const unsigned long long*)(Ws + c * WS_STRIDE);
                const unsigned long long* app = (const unsigned long long*)(apbuf + r * 32);
                #pragma unroll
                for (int a2i = 0; a2i < 16; a2i++) fma2(s2, app[a2i], wp[a2i]);
                float2 f2 = unpack2(s2);
                float  s  = val ? (f2.x + f2.y) : 0.0f;   // options value is exactly 1.0 where nonzero
                sc[ch] = s;
                cj[ch] = val ? c : -1;
                m = fmaxf(m, s);
            }
            #pragma unroll
            for (int o = 16; o > 0; o >>= 1) m = fmaxf(m, __shfl_xor_sync(FULL, m, o));

            float sum = 0.0f;
            #pragma unroll
            for (int ch = 0; ch < 3; ch++) {
                float s  = sc[ch];
                float sg = (s > 0.f) ? 1.f : ((s < 0.f) ? -1.f : 0.f);
                sum += sg * __expf(s - m * sg);
            }
            #pragma unroll
            for (int o = 16; o > 0; o >>= 1) sum += __shfl_xor_sync(FULL, sum, o);
            float lse = __logf(sum);

            // compose row in smem: zeros + scattered log-probs, then coalesced store
            __syncwarp();
            #pragma unroll
            for (int t = 0; t < 3; t++) {
                int gi = lane + 32 * t;
                if (gi < 76) *(float4*)(outbuf + 4 * gi) = make_float4(0.f, 0.f, 0.f, 0.f);
            }
            __syncwarp();
            #pragma unroll
            for (int ch = 0; ch < 3; ch++) {
                if (cj[ch] >= 0) {
                    float s  = sc[ch];
                    float sg = (s > 0.f) ? 1.f : ((s < 0.f) ? -1.f : 0.f);
                    outbuf[cj[ch]] = sg * ((s - m * sg) - lse);
                }
            }
            __syncwarp();
            float4* orow = (float4*)(Out + (size_t)(row0 + r) * C_COLS);
            #pragma unroll
            for (int t = 0; t < 3; t++) {
                int gi = lane + 32 * t;
                if (gi < 75) orow[gi] = *(const float4*)(outbuf + 4 * gi);
            }
        }
    }
}

extern "C" void kernel_launch(void* const* d_in, const int* in_sizes, int n_in,
                              void* d_out, int out_size)
{
    const float* X = (const float*)d_in[0];
    const float* W = (const float*)d_in[1];
    if (n_in >= 2 && in_sizes[0] < in_sizes[1]) {   // defensively order by size
        const float* t = X; X = W; W = t;
    }
    float* Out = (float*)d_out;

    cudaFuncSetAttribute(draftbot_kernel,
                         cudaFuncAttributeMaxDynamicSharedMemorySize, SMEM_BYTES);
    draftbot_kernel<<<GRID, THREADS, SMEM_BYTES>>>(X, W, Out);
}